// round 6
// baseline (speedup 1.0000x reference)
#include <cuda_runtime.h>
#include <cuda_bf16.h>
#include <cstdint>

// Problem shape (fixed by the dataset)
#define MM 8192
#define NN 4096
#define KK 4096

// GEMM tiling: K split -> HMMA on k<3072 (48 tiles), dp4a on k in [3072,4096) (16 tiles)
#define BM 128
#define BN 128
#define BK 64
#define STAGES 3
#define NKT_H 48
#define NJT 16
#define KSPLIT 3072
#define A_TILE_BYTES (BM * 128)
#define B_TILE_BYTES (BN * 128)
#define STAGE_BYTES (A_TILE_BYTES + B_TILE_BYTES)   // 32768
#define BF16_BYTES (STAGES * STAGE_BYTES)           // 98304
#define A8_OFF BF16_BYTES
#define A8_STAGE 16384                              // 128 rows x 128B (padded)
#define B8_OFF (A8_OFF + 2 * A8_STAGE)
#define B8_STAGE 8192                               // 128 rows x 64B
#define SMEM_TOTAL (B8_OFF + 2 * B8_STAGE)          // 147456

// Scratch (static device arrays are allowed)
__device__ __align__(16) __nv_bfloat16 g_xq[(size_t)MM * KK];
__device__ __align__(16) __nv_bfloat16 g_wb[(size_t)NN * KK];
__device__ __align__(16) int8_t g_xq8[(size_t)MM * KK];
__device__ __align__(16) int8_t g_wb8[(size_t)NN * KK];

__device__ __forceinline__ uint32_t s2u(const void* p) {
    return (uint32_t)__cvta_generic_to_shared(p);
}

// bf16 tiles: 16B-chunk index (0..7) XOR (row & 7) -> conflict-free ldmatrix
__device__ __forceinline__ uint32_t tile_addr(uint32_t base, int row, int chunk) {
    return base + row * 128 + (((uint32_t)(chunk ^ (row & 7))) << 4);
}

__device__ __forceinline__ void ldsm_x4(uint32_t& r0, uint32_t& r1,
                                        uint32_t& r2, uint32_t& r3, uint32_t a) {
    asm volatile(
        "ldmatrix.sync.aligned.m8n8.x4.shared.b16 {%0,%1,%2,%3}, [%4];"
        : "=r"(r0), "=r"(r1), "=r"(r2), "=r"(r3) : "r"(a));
}

__device__ __forceinline__ void hmma(float* c, uint32_t a0, uint32_t a1, uint32_t a2,
                                     uint32_t a3, uint32_t b0, uint32_t b1) {
    asm volatile(
        "mma.sync.aligned.m16n8k16.row.col.f32.bf16.bf16.f32 "
        "{%0,%1,%2,%3}, {%4,%5,%6,%7}, {%8,%9}, {%0,%1,%2,%3};"
        : "+f"(c[0]), "+f"(c[1]), "+f"(c[2]), "+f"(c[3])
        : "r"(a0), "r"(a1), "r"(a2), "r"(a3), "r"(b0), "r"(b1));
}

// ---------------------------------------------------------------------------
// Kernel 1: x -> bf16 + int8 of clip(round(x / s_in))
// ---------------------------------------------------------------------------
__global__ void quant_x_kernel(const float* __restrict__ x,
                               const float* __restrict__ iscale) {
    int i = blockIdx.x * blockDim.x + threadIdx.x;
    float inv = 1.0f / iscale[0];
    float4 v = reinterpret_cast<const float4*>(x)[i];
    int a0 = (int)fminf(fmaxf(rintf(v.x * inv), -128.0f), 127.0f);
    int a1 = (int)fminf(fmaxf(rintf(v.y * inv), -128.0f), 127.0f);
    int a2 = (int)fminf(fmaxf(rintf(v.z * inv), -128.0f), 127.0f);
    int a3 = (int)fminf(fmaxf(rintf(v.w * inv), -128.0f), 127.0f);
    __nv_bfloat162* o = reinterpret_cast<__nv_bfloat162*>(g_xq) + (size_t)i * 2;
    o[0] = __floats2bfloat162_rn((float)a0, (float)a1);
    o[1] = __floats2bfloat162_rn((float)a2, (float)a3);
    uint32_t p8 = (a0 & 0xff) | ((a1 & 0xff) << 8) | ((a2 & 0xff) << 16)
                | ((uint32_t)(a3 & 0xff) << 24);
    reinterpret_cast<uint32_t*>(g_xq8)[i] = p8;
}

// ---------------------------------------------------------------------------
// Kernel 2: weight int32 -> bf16 + int8 (exact)
// ---------------------------------------------------------------------------
__global__ void conv_w_kernel(const int* __restrict__ w) {
    int i = blockIdx.x * blockDim.x + threadIdx.x;
    int4 v = reinterpret_cast<const int4*>(w)[i];
    __nv_bfloat162* o = reinterpret_cast<__nv_bfloat162*>(g_wb) + (size_t)i * 2;
    o[0] = __floats2bfloat162_rn((float)v.x, (float)v.y);
    o[1] = __floats2bfloat162_rn((float)v.z, (float)v.w);
    uint32_t p8 = (v.x & 0xff) | ((v.y & 0xff) << 8) | ((v.z & 0xff) << 16)
                | ((uint32_t)(v.w & 0xff) << 24);
    reinterpret_cast<uint32_t*>(g_wb8)[i] = p8;
}

// ---------------------------------------------------------------------------
// GEMM helpers
// ---------------------------------------------------------------------------
__device__ __forceinline__ void load_stage(uint32_t sa, uint32_t sbw,
                                           const __nv_bfloat16* ak,
                                           const __nv_bfloat16* bk, int tid) {
#pragma unroll
    for (int i = 0; i < 8; ++i) {
        int c = i * 256 + tid;
        int ch = c & 7;
        int row = (c >> 3) & 127;
        uint32_t dst;
        const __nv_bfloat16* g;
        if (c < 1024) { dst = tile_addr(sa, row, ch);  g = ak + (size_t)row * KK + ch * 8; }
        else          { dst = tile_addr(sbw, row, ch); g = bk + (size_t)row * KK + ch * 8; }
        asm volatile("cp.async.cg.shared.global [%0], [%1], 16;"
                     :: "r"(dst), "l"(g) : "memory");
    }
}

// int8 tiles: A padded to 128B rows, chunk slot = ch ^ ((row>>3)&7);
//             B 64B rows, chunk slot = ch ^ ((row>>3)&3)
__device__ __forceinline__ void load_int8(uint32_t a8buf, uint32_t b8buf,
                                          const int8_t* xq8, const int8_t* wb8,
                                          int kbase, int tid) {
#pragma unroll
    for (int q = 0; q < 2; ++q) {
        int c = q * 256 + tid;
        int row = c >> 2, ch = c & 3;
        uint32_t dst = a8buf + row * 128 + ((uint32_t)(ch ^ ((row >> 3) & 7)) << 4);
        const int8_t* src = xq8 + (size_t)row * KK + kbase + ch * 16;
        asm volatile("cp.async.cg.shared.global [%0], [%1], 16;"
                     :: "r"(dst), "l"(src) : "memory");
    }
#pragma unroll
    for (int q = 0; q < 2; ++q) {
        int c = q * 256 + tid;
        int row = c >> 2, ch = c & 3;
        uint32_t dst = b8buf + row * 64 + ((uint32_t)(ch ^ ((row >> 3) & 3)) << 4);
        const int8_t* src = wb8 + (size_t)row * KK + kbase + ch * 16;
        asm volatile("cp.async.cg.shared.global [%0], [%1], 16;"
                     :: "r"(dst), "l"(src) : "memory");
    }
}

template<int S0, int S1>
__device__ __forceinline__ void dp4a_chunk(uint32_t a8b_row, uint32_t b8b_col,
                                           uint32_t axorv, uint32_t bxorv,
                                           int acci[8][8]) {
#pragma unroll
    for (int s = S0; s < S1; ++s) {
        uint32_t so = ((uint32_t)(s >> 2) << 4) | ((uint32_t)(s & 3) << 2);
        uint32_t asrc = a8b_row + (so ^ axorv);
        uint32_t bsrc = b8b_col + (so ^ bxorv);
        uint32_t aw[8], bw[8];
#pragma unroll
        for (int i = 0; i < 8; ++i)
            asm volatile("ld.shared.b32 %0, [%1];" : "=r"(aw[i]) : "r"(asrc + i * 128));
#pragma unroll
        for (int jj = 0; jj < 8; ++jj)
            asm volatile("ld.shared.b32 %0, [%1];" : "=r"(bw[jj]) : "r"(bsrc + jj * 64));
#pragma unroll
        for (int i = 0; i < 8; ++i)
#pragma unroll
            for (int jj = 0; jj < 8; ++jj)
                asm volatile("dp4a.s32.s32 %0, %1, %2, %0;"
                             : "+r"(acci[i][jj]) : "r"(aw[i]), "r"(bw[jj]));
    }
}

// ---------------------------------------------------------------------------
// Kernel 3: hybrid HMMA + dp4a GEMM
// 256 threads = 8 warps, 2x4 grid of 64x32 HMMA warp tiles; 1 CTA/SM.
// ---------------------------------------------------------------------------
__global__ void __launch_bounds__(256, 1)
gemm_kernel(float* __restrict__ out,
            const float* __restrict__ scale, const float* __restrict__ iscale) {
    extern __shared__ char smem[];
    uint32_t sb = s2u(smem);
    int tid = threadIdx.x;
    int wid = tid >> 5, lid = tid & 31;
    int wm = wid >> 2, wn = wid & 3;          // 2x4 warps, 64x32 each

    int tm = blockIdx.x & (MM / BM - 1);      // m fast -> L2 reuse
    int tn = blockIdx.x >> 6;

    const __nv_bfloat16* A  = g_xq + (size_t)tm * BM * KK;
    const __nv_bfloat16* Bw = g_wb + (size_t)tn * BN * KK;
    const int8_t* xq8 = g_xq8 + (size_t)tm * BM * KK;
    const int8_t* wb8 = g_wb8 + (size_t)tn * BN * KK;

    float acc[4][4][4];
#pragma unroll
    for (int i = 0; i < 4; ++i)
#pragma unroll
        for (int j = 0; j < 4; ++j)
#pragma unroll
            for (int k = 0; k < 4; ++k) acc[i][j][k] = 0.0f;
    int acci[8][8];
#pragma unroll
    for (int i = 0; i < 8; ++i)
#pragma unroll
        for (int j = 0; j < 8; ++j) acci[i][j] = 0;

    // HMMA ldmatrix per-lane offsets
    int lrow = lid & 15;
    uint32_t lhish = (uint32_t)(lid >> 4) << 4;
    uint32_t aoff[4], axor[4], boff[2], bxor[2];
#pragma unroll
    for (int mt = 0; mt < 4; ++mt) {
        int row = wm * 64 + mt * 16 + lrow;
        aoff[mt] = (uint32_t)row * 128;
        axor[mt] = (uint32_t)(row & 7) << 4;
    }
#pragma unroll
    for (int p = 0; p < 2; ++p) {
        int row = wn * 32 + p * 16 + lrow;
        boff[p] = (uint32_t)row * 128;
        bxor[p] = (uint32_t)(row & 7) << 4;
    }

    // dp4a per-lane bases: thread covers rows base_row..+7, cols base_col..+7
    int base_row = wm * 64 + (lid >> 2) * 8;
    int base_col = wn * 32 + (lid & 3) * 8;
    uint32_t axorv = (uint32_t)(lid >> 2) << 4;
    uint32_t bxorv = (uint32_t)(lid & 3) << 4;

    // prologue: group0 = bf16 tile0 + int8 tile0; group1 = bf16 tile1
    load_stage(sb, sb + A_TILE_BYTES, A, Bw, tid);
    load_int8(sb + A8_OFF, sb + B8_OFF, xq8, wb8, KSPLIT, tid);
    asm volatile("cp.async.commit_group;" ::: "memory");
    load_stage(sb + STAGE_BYTES, sb + STAGE_BYTES + A_TILE_BYTES,
               A + BK, Bw + BK, tid);
    asm volatile("cp.async.commit_group;" ::: "memory");

    for (int jt = 0; jt < NJT; ++jt) {
#pragma unroll
        for (int p = 0; p < 3; ++p) {
            asm volatile("cp.async.wait_group %0;" :: "n"(STAGES - 2) : "memory");
            __syncthreads();

            // loads for iter kt+2
            int ktn = jt * 3 + p + 2;
            if (ktn < NKT_H) {
                uint32_t st2 = sb + ((p + 2) % 3) * STAGE_BYTES;
                load_stage(st2, st2 + A_TILE_BYTES,
                           A + (size_t)ktn * BK, Bw + (size_t)ktn * BK, tid);
            }
            if (p == 1 && jt < NJT - 1) {
                int jn = jt + 1;
                load_int8(sb + A8_OFF + (jn & 1) * A8_STAGE,
                          sb + B8_OFF + (jn & 1) * B8_STAGE,
                          xq8, wb8, KSPLIT + jn * BK, tid);
            }
            asm volatile("cp.async.commit_group;" ::: "memory");

            // HMMA on bf16 stage p
            uint32_t sa = sb + p * STAGE_BYTES, sbw = sa + A_TILE_BYTES;
#pragma unroll
            for (int j = 0; j < 4; ++j) {
                uint32_t chsh = ((uint32_t)(2 * j) << 4) ^ lhish;
                uint32_t fa[4][4], fb[2][4];
#pragma unroll
                for (int mt = 0; mt < 4; ++mt)
                    ldsm_x4(fa[mt][0], fa[mt][1], fa[mt][2], fa[mt][3],
                            sa + aoff[mt] + (chsh ^ axor[mt]));
#pragma unroll
                for (int q = 0; q < 2; ++q)
                    ldsm_x4(fb[q][0], fb[q][1], fb[q][2], fb[q][3],
                            sbw + boff[q] + (chsh ^ bxor[q]));
#pragma unroll
                for (int mt = 0; mt < 4; ++mt)
#pragma unroll
                    for (int q = 0; q < 2; ++q) {
                        hmma(acc[mt][2 * q],     fa[mt][0], fa[mt][1], fa[mt][2],
                             fa[mt][3], fb[q][0], fb[q][2]);
                        hmma(acc[mt][2 * q + 1], fa[mt][0], fa[mt][1], fa[mt][2],
                             fa[mt][3], fb[q][1], fb[q][3]);
                    }
            }

            // dp4a on int8 tile jt (16 k4 steps split 6/5/5 across phases)
            uint32_t a8b_row = sb + A8_OFF + (jt & 1) * A8_STAGE + base_row * 128;
            uint32_t b8b_col = sb + B8_OFF + (jt & 1) * B8_STAGE + base_col * 64;
            if (p == 0)      dp4a_chunk<0, 6>(a8b_row, b8b_col, axorv, bxorv, acci);
            else if (p == 1) dp4a_chunk<6, 11>(a8b_row, b8b_col, axorv, bxorv, acci);
            else             dp4a_chunk<11, 16>(a8b_row, b8b_col, axorv, bxorv, acci);
        }
    }

    // drain async FIFO, then overlay int accumulators into smem
    asm volatile("cp.async.wait_all;" ::: "memory");
    __syncthreads();
    int* sacc = reinterpret_cast<int*>(smem);
#pragma unroll
    for (int i = 0; i < 8; ++i)
#pragma unroll
        for (int jj = 0; jj < 8; ++jj)
            sacc[(base_row + i) * 128 + base_col + jj] = acci[i][jj];
    __syncthreads();

    // epilogue: merge HMMA fp32 + dp4a int parts, scale, store
    float cs = scale[0] * iscale[0];
    int r0 = lid >> 2, c0 = (lid & 3) * 2;
#pragma unroll
    for (int mt = 0; mt < 4; ++mt) {
        int mrow = wm * 64 + mt * 16 + r0;
        size_t grow = (size_t)tm * BM + mrow;
#pragma unroll
        for (int nt = 0; nt < 4; ++nt) {
            int ncol = wn * 32 + nt * 8 + c0;
            size_t gcol = (size_t)tn * BN + ncol;
            float2 v0, v1;
            v0.x = (acc[mt][nt][0] + (float)sacc[mrow * 128 + ncol]) * cs;
            v0.y = (acc[mt][nt][1] + (float)sacc[mrow * 128 + ncol + 1]) * cs;
            v1.x = (acc[mt][nt][2] + (float)sacc[(mrow + 8) * 128 + ncol]) * cs;
            v1.y = (acc[mt][nt][3] + (float)sacc[(mrow + 8) * 128 + ncol + 1]) * cs;
            *reinterpret_cast<float2*>(out + grow * NN + gcol) = v0;
            *reinterpret_cast<float2*>(out + (grow + 8) * NN + gcol) = v1;
        }
    }
}

// ---------------------------------------------------------------------------
extern "C" void kernel_launch(void* const* d_in, const int* in_sizes, int n_in,
                              void* d_out, int out_size) {
    const float* x      = (const float*)d_in[0];
    const int*   w      = (const int*)d_in[1];
    const float* scale  = (const float*)d_in[2];
    const float* iscale = (const float*)d_in[3];
    float* out = (float*)d_out;

    cudaFuncSetAttribute(gemm_kernel, cudaFuncAttributeMaxDynamicSharedMemorySize,
                         SMEM_TOTAL);

    quant_x_kernel<<<(MM * KK / 4) / 256, 256>>>(x, iscale);
    conv_w_kernel<<<(NN * KK / 4) / 256, 256>>>(w);
    gemm_kernel<<<(MM / BM) * (NN / BN), 256, SMEM_TOTAL>>>(out, scale, iscale);
}

// round 7
// speedup vs baseline: 1.4990x; 1.4990x over previous
#include <cuda_runtime.h>
#include <cuda_fp16.h>
#include <cstdint>

// Problem shape (fixed by the dataset)
#define MM 8192
#define NN 4096
#define KK 4096

// GEMM tiling (fp16 operands)
#define BM 128
#define BN 128
#define BK 64               // fp16 elems = 128 bytes = one swizzled row
#define STAGES 3
#define NKT (KK / BK)       // 64
#define A_TILE_BYTES (BM * 128)          // 16384
#define B_TILE_BYTES (BN * 128)          // 16384
#define STAGE_BYTES (A_TILE_BYTES + B_TILE_BYTES)   // 32768
#define SMEM_TOTAL (STAGES * STAGE_BYTES)           // 98304 -> 2 CTAs/SM

// Scratch: quantized activations + fp16 weights (static device arrays allowed)
__device__ __align__(16) __half g_xq[(size_t)MM * KK];
__device__ __align__(16) __half g_wb[(size_t)NN * KK];

__device__ __forceinline__ uint32_t s2u(const void* p) {
    return (uint32_t)__cvta_generic_to_shared(p);
}

// XOR swizzle: 16B-chunk index (0..7) XOR (row & 7) -> conflict-free ldmatrix
__device__ __forceinline__ uint32_t tile_addr(uint32_t base, int row, int chunk) {
    return base + row * 128 + (((uint32_t)(chunk ^ (row & 7))) << 4);
}

__device__ __forceinline__ void ldsm_x4(uint32_t& r0, uint32_t& r1,
                                        uint32_t& r2, uint32_t& r3, uint32_t a) {
    asm volatile(
        "ldmatrix.sync.aligned.m8n8.x4.shared.b16 {%0,%1,%2,%3}, [%4];"
        : "=r"(r0), "=r"(r1), "=r"(r2), "=r"(r3) : "r"(a));
}

__device__ __forceinline__ void hmma(float* c, uint32_t a0, uint32_t a1, uint32_t a2,
                                     uint32_t a3, uint32_t b0, uint32_t b1) {
    asm volatile(
        "mma.sync.aligned.m16n8k16.row.col.f32.f16.f16.f32 "
        "{%0,%1,%2,%3}, {%4,%5,%6,%7}, {%8,%9}, {%0,%1,%2,%3};"
        : "+f"(c[0]), "+f"(c[1]), "+f"(c[2]), "+f"(c[3])
        : "r"(a0), "r"(a1), "r"(a2), "r"(a3), "r"(b0), "r"(b1));
}

// ---------------------------------------------------------------------------
// Kernel 1 (fused prep): blocks [0, 8192)  : x -> fp16(clip(round(x/s_in)))
//                        blocks [8192, ...) : W int32 -> fp16 (exact)
// Each block handles 1024 elements via 256 threads x 4-wide vectors.
// ---------------------------------------------------------------------------
#define XBLOCKS ((MM * KK / 4) / 256)   // 32768 / 4-wide / 256 thr = 8192
#define WBLOCKS ((NN * KK / 4) / 256)   // 4096... = 16384/4=... computed below

__global__ void prep_kernel(const float* __restrict__ x,
                            const int* __restrict__ w,
                            const float* __restrict__ iscale) {
    int b = blockIdx.x;
    if (b < XBLOCKS) {
        int i = b * 256 + threadIdx.x;
        float inv = 1.0f / iscale[0];
        float4 v = reinterpret_cast<const float4*>(x)[i];
        float a0 = fminf(fmaxf(rintf(v.x * inv), -128.0f), 127.0f);
        float a1 = fminf(fmaxf(rintf(v.y * inv), -128.0f), 127.0f);
        float a2 = fminf(fmaxf(rintf(v.z * inv), -128.0f), 127.0f);
        float a3 = fminf(fmaxf(rintf(v.w * inv), -128.0f), 127.0f);
        __half2* o = reinterpret_cast<__half2*>(g_xq) + (size_t)i * 2;
        o[0] = __floats2half2_rn(a0, a1);
        o[1] = __floats2half2_rn(a2, a3);
    } else {
        int i = (b - XBLOCKS) * 256 + threadIdx.x;
        int4 v = reinterpret_cast<const int4*>(w)[i];
        __half2* o = reinterpret_cast<__half2*>(g_wb) + (size_t)i * 2;
        o[0] = __floats2half2_rn((float)v.x, (float)v.y);
        o[1] = __floats2half2_rn((float)v.z, (float)v.w);
    }
}

// ---------------------------------------------------------------------------
// Kernel 2: fp16 HMMA GEMM  out[m,n] = (sum_k A[m,k]*W[n,k]) * cs
// 256 threads = 8 warps in a 2x4 grid of 64x32 warp tiles; 2 CTAs/SM.
// ---------------------------------------------------------------------------
__device__ __forceinline__ void load_stage(uint32_t sa, uint32_t sbw,
                                           const __half* ak,
                                           const __half* bk, int tid) {
    // 2048 16B chunks (A: 1024, B: 1024), 8 per thread, chunk-fastest coalesced
#pragma unroll
    for (int i = 0; i < 8; ++i) {
        int c = i * 256 + tid;
        int ch = c & 7;
        int row = (c >> 3) & 127;
        uint32_t dst;
        const __half* g;
        if (c < 1024) {
            dst = tile_addr(sa, row, ch);
            g = ak + (size_t)row * KK + ch * 8;
        } else {
            dst = tile_addr(sbw, row, ch);
            g = bk + (size_t)row * KK + ch * 8;
        }
        asm volatile("cp.async.cg.shared.global [%0], [%1], 16;"
                     :: "r"(dst), "l"(g) : "memory");
    }
}

__global__ void __launch_bounds__(256, 2)
gemm_kernel(float* __restrict__ out,
            const float* __restrict__ scale, const float* __restrict__ iscale) {
    extern __shared__ char smem[];
    uint32_t sb = s2u(smem);
    int tid = threadIdx.x;
    int wid = tid >> 5, lid = tid & 31;
    int wm = wid >> 2, wn = wid & 3;          // 2x4 warps, 64x32 each

    int tm = blockIdx.x & (MM / BM - 1);      // m fast -> ktile slices stay in L2
    int tn = blockIdx.x >> 6;                 // MM/BM = 64

    const __half* A  = g_xq + (size_t)tm * BM * KK;
    const __half* Bw = g_wb + (size_t)tn * BN * KK;

    float acc[4][4][4];                        // [m16][n8][frag] = 64 regs
#pragma unroll
    for (int i = 0; i < 4; ++i)
#pragma unroll
        for (int j = 0; j < 4; ++j)
#pragma unroll
            for (int k = 0; k < 4; ++k) acc[i][j][k] = 0.0f;

    // per-lane LDSM base offsets (row*128) and swizzle XOR terms ((row&7)<<4)
    int lrow = lid & 15;                       // row within 16-row block
    uint32_t lhish = (uint32_t)(lid >> 4) << 4;
    uint32_t aoff[4], axor[4], boff[2], bxor[2];
#pragma unroll
    for (int mt = 0; mt < 4; ++mt) {
        int row = wm * 64 + mt * 16 + lrow;
        aoff[mt] = (uint32_t)row * 128;
        axor[mt] = (uint32_t)(row & 7) << 4;
    }
#pragma unroll
    for (int p = 0; p < 2; ++p) {
        int row = wn * 32 + p * 16 + lrow;
        boff[p] = (uint32_t)row * 128;
        bxor[p] = (uint32_t)(row & 7) << 4;
    }

    // prologue: fill STAGES-1 stages
#pragma unroll
    for (int s = 0; s < STAGES - 1; ++s) {
        load_stage(sb + s * STAGE_BYTES, sb + s * STAGE_BYTES + A_TILE_BYTES,
                   A + (size_t)s * BK, Bw + (size_t)s * BK, tid);
        asm volatile("cp.async.commit_group;" ::: "memory");
    }

    for (int kt = 0; kt < NKT; ++kt) {
        uint32_t st = sb + (kt % STAGES) * STAGE_BYTES;
        uint32_t sa = st, sbw = st + A_TILE_BYTES;
        asm volatile("cp.async.wait_group %0;" :: "n"(STAGES - 2) : "memory");
        __syncthreads();   // stage kt arrived; stage kt-1 fully consumed by all warps

        // issue next tile's loads FIRST (into the stage consumed at kt-1)
        int ktn = kt + STAGES - 1;
        if (ktn < NKT) {
            uint32_t st2 = sb + (ktn % STAGES) * STAGE_BYTES;
            load_stage(st2, st2 + A_TILE_BYTES,
                       A + (size_t)ktn * BK, Bw + (size_t)ktn * BK, tid);
        }
        asm volatile("cp.async.commit_group;" ::: "memory");

#pragma unroll
        for (int j = 0; j < 4; ++j) {          // 4 k-steps of 16
            uint32_t chsh = ((uint32_t)(2 * j) << 4) ^ lhish;
            uint32_t fa[4][4], fb[2][4];
#pragma unroll
            for (int mt = 0; mt < 4; ++mt)
                ldsm_x4(fa[mt][0], fa[mt][1], fa[mt][2], fa[mt][3],
                        sa + aoff[mt] + (chsh ^ axor[mt]));
#pragma unroll
            for (int p = 0; p < 2; ++p)
                ldsm_x4(fb[p][0], fb[p][1], fb[p][2], fb[p][3],
                        sbw + boff[p] + (chsh ^ bxor[p]));
#pragma unroll
            for (int mt = 0; mt < 4; ++mt)
#pragma unroll
                for (int p = 0; p < 2; ++p) {
                    hmma(acc[mt][2 * p],     fa[mt][0], fa[mt][1], fa[mt][2],
                         fa[mt][3], fb[p][0], fb[p][2]);
                    hmma(acc[mt][2 * p + 1], fa[mt][0], fa[mt][1], fa[mt][2],
                         fa[mt][3], fb[p][1], fb[p][3]);
                }
        }
    }

    // epilogue: scale and store fp32
    float cs = scale[0] * iscale[0];
    int r0 = lid >> 2, c0 = (lid & 3) * 2;
#pragma unroll
    for (int mt = 0; mt < 4; ++mt) {
        size_t row0 = (size_t)tm * BM + wm * 64 + mt * 16 + r0;
#pragma unroll
        for (int nt = 0; nt < 4; ++nt) {
            size_t col = (size_t)tn * BN + wn * 32 + nt * 8 + c0;
            float2 v0, v1;
            v0.x = acc[mt][nt][0] * cs;
            v0.y = acc[mt][nt][1] * cs;
            v1.x = acc[mt][nt][2] * cs;
            v1.y = acc[mt][nt][3] * cs;
            *reinterpret_cast<float2*>(out + row0 * NN + col) = v0;
            *reinterpret_cast<float2*>(out + (row0 + 8) * NN + col) = v1;
        }
    }
}

// ---------------------------------------------------------------------------
extern "C" void kernel_launch(void* const* d_in, const int* in_sizes, int n_in,
                              void* d_out, int out_size) {
    const float* x      = (const float*)d_in[0];
    const int*   w      = (const int*)d_in[1];
    const float* scale  = (const float*)d_in[2];
    const float* iscale = (const float*)d_in[3];
    float* out = (float*)d_out;

    cudaFuncSetAttribute(gemm_kernel, cudaFuncAttributeMaxDynamicSharedMemorySize,
                         SMEM_TOTAL);

    int wblocks = (NN * KK / 4) / 256;
    prep_kernel<<<XBLOCKS + wblocks, 256>>>(x, w, iscale);
    gemm_kernel<<<(MM / BM) * (NN / BN), 256, SMEM_TOTAL>>>(out, scale, iscale);
}

// round 8
// speedup vs baseline: 1.5395x; 1.0270x over previous
#include <cuda_runtime.h>
#include <cuda_fp16.h>
#include <cstdint>

// Problem shape (fixed by the dataset)
#define MM 8192
#define NN 4096
#define KK 4096

// GEMM tiling (fp16 operands)
#define BM 128
#define BN 128
#define BK 64               // fp16 elems = 128 bytes = one swizzled row
#define STAGES 3
#define NKT (KK / BK)       // 64
#define A_TILE_BYTES (BM * 128)          // 16384
#define B_TILE_BYTES (BN * 128)          // 16384
#define STAGE_BYTES (A_TILE_BYTES + B_TILE_BYTES)   // 32768
#define SMEM_TOTAL (STAGES * STAGE_BYTES)           // 98304 -> 2 CTAs/SM

#define ROW_BYTES (KK * 2)               // 8192 bytes per logical row
#define I_GSTRIDE (32 * ROW_BYTES)       // 262144: +32 rows in gmem
#define I_SSTRIDE (32 * 128)             // 4096:   +32 rows in smem tile

// Scratch: quantized activations + fp16 weights (static device arrays allowed)
__device__ __align__(16) __half g_xq[(size_t)MM * KK];
__device__ __align__(16) __half g_wb[(size_t)NN * KK];

__device__ __forceinline__ uint32_t s2u(const void* p) {
    return (uint32_t)__cvta_generic_to_shared(p);
}

__device__ __forceinline__ void ldsm_x4(uint32_t& r0, uint32_t& r1,
                                        uint32_t& r2, uint32_t& r3, uint32_t a) {
    asm volatile(
        "ldmatrix.sync.aligned.m8n8.x4.shared.b16 {%0,%1,%2,%3}, [%4];"
        : "=r"(r0), "=r"(r1), "=r"(r2), "=r"(r3) : "r"(a));
}

__device__ __forceinline__ void hmma(float* c, uint32_t a0, uint32_t a1, uint32_t a2,
                                     uint32_t a3, uint32_t b0, uint32_t b1) {
    asm volatile(
        "mma.sync.aligned.m16n8k16.row.col.f32.f16.f16.f32 "
        "{%0,%1,%2,%3}, {%4,%5,%6,%7}, {%8,%9}, {%0,%1,%2,%3};"
        : "+f"(c[0]), "+f"(c[1]), "+f"(c[2]), "+f"(c[3])
        : "r"(a0), "r"(a1), "r"(a2), "r"(a3), "r"(b0), "r"(b1));
}

__device__ __forceinline__ void cpa16(uint32_t dst, const void* src) {
    asm volatile("cp.async.cg.shared.global [%0], [%1], 16;"
                 :: "r"(dst), "l"(src) : "memory");
}

// ---------------------------------------------------------------------------
// Kernel 1 (fused prep, 2-wide ILP):
//   blocks [0, 16384)     : x -> fp16(clip(round(x/s_in)))   (2 float4/thread)
//   blocks [16384, 24576) : W int32 -> fp16 (exact)          (2 int4/thread)
// ---------------------------------------------------------------------------
#define XQ4 (MM * KK / 4)     // 8388608 float4s
#define WQ4 (NN * KK / 4)     // 4194304 int4s
#define XBLK (XQ4 / 2 / 256)  // 16384
#define WBLK (WQ4 / 2 / 256)  // 8192

__global__ void prep_kernel(const float* __restrict__ x,
                            const int* __restrict__ w,
                            const float* __restrict__ iscale) {
    int b = blockIdx.x;
    if (b < XBLK) {
        int i = b * 256 + threadIdx.x;
        float inv = 1.0f / iscale[0];
        float4 v0 = reinterpret_cast<const float4*>(x)[i];
        float4 v1 = reinterpret_cast<const float4*>(x)[i + XQ4 / 2];
        float a0 = fminf(fmaxf(rintf(v0.x * inv), -128.0f), 127.0f);
        float a1 = fminf(fmaxf(rintf(v0.y * inv), -128.0f), 127.0f);
        float a2 = fminf(fmaxf(rintf(v0.z * inv), -128.0f), 127.0f);
        float a3 = fminf(fmaxf(rintf(v0.w * inv), -128.0f), 127.0f);
        float b0 = fminf(fmaxf(rintf(v1.x * inv), -128.0f), 127.0f);
        float b1 = fminf(fmaxf(rintf(v1.y * inv), -128.0f), 127.0f);
        float b2 = fminf(fmaxf(rintf(v1.z * inv), -128.0f), 127.0f);
        float b3 = fminf(fmaxf(rintf(v1.w * inv), -128.0f), 127.0f);
        __half2* o0 = reinterpret_cast<__half2*>(g_xq) + (size_t)i * 2;
        __half2* o1 = reinterpret_cast<__half2*>(g_xq) + ((size_t)i + XQ4 / 2) * 2;
        o0[0] = __floats2half2_rn(a0, a1);
        o0[1] = __floats2half2_rn(a2, a3);
        o1[0] = __floats2half2_rn(b0, b1);
        o1[1] = __floats2half2_rn(b2, b3);
    } else {
        int i = (b - XBLK) * 256 + threadIdx.x;
        int4 v0 = reinterpret_cast<const int4*>(w)[i];
        int4 v1 = reinterpret_cast<const int4*>(w)[i + WQ4 / 2];
        __half2* o0 = reinterpret_cast<__half2*>(g_wb) + (size_t)i * 2;
        __half2* o1 = reinterpret_cast<__half2*>(g_wb) + ((size_t)i + WQ4 / 2) * 2;
        o0[0] = __floats2half2_rn((float)v0.x, (float)v0.y);
        o0[1] = __floats2half2_rn((float)v0.z, (float)v0.w);
        o1[0] = __floats2half2_rn((float)v1.x, (float)v1.y);
        o1[1] = __floats2half2_rn((float)v1.z, (float)v1.w);
    }
}

// ---------------------------------------------------------------------------
// Kernel 2: fp16 HMMA GEMM  out[m,n] = (sum_k A[m,k]*W[n,k]) * cs
// 256 threads = 8 warps in a 2x4 grid of 64x32 warp tiles; 2 CTAs/SM.
// Per-thread cp.async addressing reduced to 2 base pointers + 2 smem offsets.
// ---------------------------------------------------------------------------
__global__ void __launch_bounds__(256, 2)
gemm_kernel(float* __restrict__ out,
            const float* __restrict__ scale, const float* __restrict__ iscale) {
    extern __shared__ char smem[];
    uint32_t sb = s2u(smem);
    int tid = threadIdx.x;
    int wid = tid >> 5, lid = tid & 31;
    int wm = wid >> 2, wn = wid & 3;          // 2x4 warps, 64x32 each

    int tm = blockIdx.x & (MM / BM - 1);      // m fast -> ktile slices stay in L2
    int tn = blockIdx.x >> 6;                 // MM/BM = 64

    // per-thread cp.async bases (row = tid>>3 within 32-row group, ch = tid&7)
    int prow = tid >> 3, pch = tid & 7;
    const char* aptr = reinterpret_cast<const char*>(g_xq)
                     + (size_t)(tm * BM + prow) * ROW_BYTES + pch * 16;
    const char* bptr = reinterpret_cast<const char*>(g_wb)
                     + (size_t)(tn * BN + prow) * ROW_BYTES + pch * 16;
    uint32_t dbase_a = (uint32_t)prow * 128
                     + ((uint32_t)(pch ^ (prow & 7)) << 4);
    uint32_t dbase_b = dbase_a + A_TILE_BYTES;

    float acc[4][4][4];                        // [m16][n8][frag] = 64 regs
#pragma unroll
    for (int i = 0; i < 4; ++i)
#pragma unroll
        for (int j = 0; j < 4; ++j)
#pragma unroll
            for (int k = 0; k < 4; ++k) acc[i][j][k] = 0.0f;

    // per-lane LDSM base offsets (row*128) and swizzle XOR terms ((row&7)<<4)
    int lrow = lid & 15;
    uint32_t lhish = (uint32_t)(lid >> 4) << 4;
    uint32_t aoff[4], axor[4], boff[2], bxor[2];
#pragma unroll
    for (int mt = 0; mt < 4; ++mt) {
        int row = wm * 64 + mt * 16 + lrow;
        aoff[mt] = (uint32_t)row * 128;
        axor[mt] = (uint32_t)(row & 7) << 4;
    }
#pragma unroll
    for (int p = 0; p < 2; ++p) {
        int row = wn * 32 + p * 16 + lrow;
        boff[p] = (uint32_t)row * 128;
        bxor[p] = (uint32_t)(row & 7) << 4;
    }

    // prologue: fill STAGES-1 stages
#pragma unroll
    for (int s = 0; s < STAGES - 1; ++s) {
#pragma unroll
        for (int i = 0; i < 4; ++i)
            cpa16(sb + s * STAGE_BYTES + dbase_a + i * I_SSTRIDE,
                  aptr + i * I_GSTRIDE);
#pragma unroll
        for (int i = 0; i < 4; ++i)
            cpa16(sb + s * STAGE_BYTES + dbase_b + i * I_SSTRIDE,
                  bptr + i * I_GSTRIDE);
        asm volatile("cp.async.commit_group;" ::: "memory");
        aptr += BK * 2;
        bptr += BK * 2;
    }

    uint32_t cur = sb;                                   // stage being computed
    uint32_t lda = sb + (STAGES - 1) * STAGE_BYTES + dbase_a;  // load target
    uint32_t ldb = sb + (STAGES - 1) * STAGE_BYTES + dbase_b;
    const uint32_t wrap = sb + STAGES * STAGE_BYTES;

    for (int kt = 0; kt < NKT; ++kt) {
        asm volatile("cp.async.wait_group %0;" :: "n"(STAGES - 2) : "memory");
        __syncthreads();   // stage kt arrived; stage kt-1 fully consumed

        uint32_t sa = cur, sbw = cur + A_TILE_BYTES;

        // j = 0 fragments first: restart the tensor pipe immediately
        uint32_t fa[4][4], fb[2][4];
        {
            uint32_t chsh = lhish;
#pragma unroll
            for (int mt = 0; mt < 4; ++mt)
                ldsm_x4(fa[mt][0], fa[mt][1], fa[mt][2], fa[mt][3],
                        sa + aoff[mt] + (chsh ^ axor[mt]));
#pragma unroll
            for (int p = 0; p < 2; ++p)
                ldsm_x4(fb[p][0], fb[p][1], fb[p][2], fb[p][3],
                        sbw + boff[p] + (chsh ^ bxor[p]));
        }

        // issue next tile's loads (cheap addressing: base + imm)
        if (kt < NKT - (STAGES - 1)) {
#pragma unroll
            for (int i = 0; i < 4; ++i)
                cpa16(lda + i * I_SSTRIDE, aptr + i * I_GSTRIDE);
#pragma unroll
            for (int i = 0; i < 4; ++i)
                cpa16(ldb + i * I_SSTRIDE, bptr + i * I_GSTRIDE);
            aptr += BK * 2;
            bptr += BK * 2;
        }
        asm volatile("cp.async.commit_group;" ::: "memory");

#pragma unroll
        for (int j = 0; j < 4; ++j) {          // 4 k-steps of 16
            // compute j, prefetching j+1 fragments after the HMMAs are issued
            uint32_t ga[4][4], gb[2][4];
#pragma unroll
            for (int mt = 0; mt < 4; ++mt)
#pragma unroll
                for (int p = 0; p < 2; ++p) {
                    hmma(acc[mt][2 * p],     fa[mt][0], fa[mt][1], fa[mt][2],
                         fa[mt][3], fb[p][0], fb[p][2]);
                    hmma(acc[mt][2 * p + 1], fa[mt][0], fa[mt][1], fa[mt][2],
                         fa[mt][3], fb[p][1], fb[p][3]);
                }
            if (j < 3) {
                uint32_t chsh = ((uint32_t)(2 * (j + 1)) << 4) ^ lhish;
#pragma unroll
                for (int mt = 0; mt < 4; ++mt)
                    ldsm_x4(ga[mt][0], ga[mt][1], ga[mt][2], ga[mt][3],
                            sa + aoff[mt] + (chsh ^ axor[mt]));
#pragma unroll
                for (int p = 0; p < 2; ++p)
                    ldsm_x4(gb[p][0], gb[p][1], gb[p][2], gb[p][3],
                            sbw + boff[p] + (chsh ^ bxor[p]));
#pragma unroll
                for (int mt = 0; mt < 4; ++mt)
#pragma unroll
                    for (int q = 0; q < 4; ++q) fa[mt][q] = ga[mt][q];
#pragma unroll
                for (int p = 0; p < 2; ++p)
#pragma unroll
                    for (int q = 0; q < 4; ++q) fb[p][q] = gb[p][q];
            }
        }

        // rotate stages
        cur += STAGE_BYTES; if (cur == wrap) cur = sb;
        lda += STAGE_BYTES; if (lda >= wrap) lda -= STAGES * STAGE_BYTES;
        ldb += STAGE_BYTES; if (ldb >= wrap) ldb -= STAGES * STAGE_BYTES;
    }

    // epilogue: scale and store fp32
    float cs = scale[0] * iscale[0];
    int r0 = lid >> 2, c0 = (lid & 3) * 2;
#pragma unroll
    for (int mt = 0; mt < 4; ++mt) {
        size_t row0 = (size_t)tm * BM + wm * 64 + mt * 16 + r0;
#pragma unroll
        for (int nt = 0; nt < 4; ++nt) {
            size_t col = (size_t)tn * BN + wn * 32 + nt * 8 + c0;
            float2 v0, v1;
            v0.x = acc[mt][nt][0] * cs;
            v0.y = acc[mt][nt][1] * cs;
            v1.x = acc[mt][nt][2] * cs;
            v1.y = acc[mt][nt][3] * cs;
            *reinterpret_cast<float2*>(out + row0 * NN + col) = v0;
            *reinterpret_cast<float2*>(out + (row0 + 8) * NN + col) = v1;
        }
    }
}

// ---------------------------------------------------------------------------
extern "C" void kernel_launch(void* const* d_in, const int* in_sizes, int n_in,
                              void* d_out, int out_size) {
    const float* x      = (const float*)d_in[0];
    const int*   w      = (const int*)d_in[1];
    const float* scale  = (const float*)d_in[2];
    const float* iscale = (const float*)d_in[3];
    float* out = (float*)d_out;

    cudaFuncSetAttribute(gemm_kernel, cudaFuncAttributeMaxDynamicSharedMemorySize,
                         SMEM_TOTAL);

    prep_kernel<<<XBLK + WBLK, 256>>>(x, w, iscale);
    gemm_kernel<<<(MM / BM) * (NN / BN), 256, SMEM_TOTAL>>>(out, scale, iscale);
}

// round 10
// speedup vs baseline: 1.5654x; 1.0168x over previous
#include <cuda_runtime.h>
#include <cuda_fp16.h>
#include <cstdint>

// Problem shape (fixed by the dataset)
#define MM 8192
#define NN 4096
#define KK 4096

// GEMM tiling (fp16 operands)
#define BM 128
#define BN 128
#define BK 64               // fp16 elems = 128 bytes = one swizzled row
#define STAGES 3
#define NKT (KK / BK)       // 64
#define A_TILE_BYTES (BM * 128)          // 16384
#define B_TILE_BYTES (BN * 128)          // 16384
#define STAGE_BYTES (A_TILE_BYTES + B_TILE_BYTES)   // 32768
#define SMEM_TOTAL (STAGES * STAGE_BYTES)           // 98304 -> 2 CTAs/SM

#define ROW_BYTES (KK * 2)               // 8192 bytes per logical row
#define I_GSTRIDE (16 * ROW_BYTES)       // +16 rows in gmem (128 threads)
#define I_SSTRIDE (16 * 128)             // +16 rows in smem tile

// Scratch: quantized activations + fp16 weights (static device arrays allowed)
__device__ __align__(16) __half g_xq[(size_t)MM * KK];
__device__ __align__(16) __half g_wb[(size_t)NN * KK];

__device__ __forceinline__ uint32_t s2u(const void* p) {
    return (uint32_t)__cvta_generic_to_shared(p);
}

__device__ __forceinline__ void ldsm_x4(uint32_t& r0, uint32_t& r1,
                                        uint32_t& r2, uint32_t& r3, uint32_t a) {
    asm volatile(
        "ldmatrix.sync.aligned.m8n8.x4.shared.b16 {%0,%1,%2,%3}, [%4];"
        : "=r"(r0), "=r"(r1), "=r"(r2), "=r"(r3) : "r"(a));
}

__device__ __forceinline__ void hmma(float* c, uint32_t a0, uint32_t a1, uint32_t a2,
                                     uint32_t a3, uint32_t b0, uint32_t b1) {
    asm volatile(
        "mma.sync.aligned.m16n8k16.row.col.f32.f16.f16.f32 "
        "{%0,%1,%2,%3}, {%4,%5,%6,%7}, {%8,%9}, {%0,%1,%2,%3};"
        : "+f"(c[0]), "+f"(c[1]), "+f"(c[2]), "+f"(c[3])
        : "r"(a0), "r"(a1), "r"(a2), "r"(a3), "r"(b0), "r"(b1));
}

__device__ __forceinline__ void cpa16(uint32_t dst, const void* src) {
    asm volatile("cp.async.cg.shared.global [%0], [%1], 16;"
                 :: "r"(dst), "l"(src) : "memory");
}

// ---------------------------------------------------------------------------
// Kernel 1 (fused prep, 2-wide ILP):
//   blocks [0, XBLK)          : x -> fp16(clip(round(x/s_in)))
//   blocks [XBLK, XBLK+WBLK)  : W int32 -> fp16 (exact)
// ---------------------------------------------------------------------------
#define XQ4 (MM * KK / 4)
#define WQ4 (NN * KK / 4)
#define XBLK (XQ4 / 2 / 256)
#define WBLK (WQ4 / 2 / 256)

__global__ void prep_kernel(const float* __restrict__ x,
                            const int* __restrict__ w,
                            const float* __restrict__ iscale) {
    int b = blockIdx.x;
    if (b < XBLK) {
        int i = b * 256 + threadIdx.x;
        float inv = 1.0f / iscale[0];
        float4 v0 = reinterpret_cast<const float4*>(x)[i];
        float4 v1 = reinterpret_cast<const float4*>(x)[i + XQ4 / 2];
        float a0 = fminf(fmaxf(rintf(v0.x * inv), -128.0f), 127.0f);
        float a1 = fminf(fmaxf(rintf(v0.y * inv), -128.0f), 127.0f);
        float a2 = fminf(fmaxf(rintf(v0.z * inv), -128.0f), 127.0f);
        float a3 = fminf(fmaxf(rintf(v0.w * inv), -128.0f), 127.0f);
        float b0 = fminf(fmaxf(rintf(v1.x * inv), -128.0f), 127.0f);
        float b1 = fminf(fmaxf(rintf(v1.y * inv), -128.0f), 127.0f);
        float b2 = fminf(fmaxf(rintf(v1.z * inv), -128.0f), 127.0f);
        float b3 = fminf(fmaxf(rintf(v1.w * inv), -128.0f), 127.0f);
        __half2* o0 = reinterpret_cast<__half2*>(g_xq) + (size_t)i * 2;
        __half2* o1 = reinterpret_cast<__half2*>(g_xq) + ((size_t)i + XQ4 / 2) * 2;
        o0[0] = __floats2half2_rn(a0, a1);
        o0[1] = __floats2half2_rn(a2, a3);
        o1[0] = __floats2half2_rn(b0, b1);
        o1[1] = __floats2half2_rn(b2, b3);
    } else {
        int i = (b - XBLK) * 256 + threadIdx.x;
        int4 v0 = reinterpret_cast<const int4*>(w)[i];
        int4 v1 = reinterpret_cast<const int4*>(w)[i + WQ4 / 2];
        __half2* o0 = reinterpret_cast<__half2*>(g_wb) + (size_t)i * 2;
        __half2* o1 = reinterpret_cast<__half2*>(g_wb) + ((size_t)i + WQ4 / 2) * 2;
        o0[0] = __floats2half2_rn((float)v0.x, (float)v0.y);
        o0[1] = __floats2half2_rn((float)v0.z, (float)v0.w);
        o1[0] = __floats2half2_rn((float)v1.x, (float)v1.y);
        o1[1] = __floats2half2_rn((float)v1.z, (float)v1.w);
    }
}

// ---------------------------------------------------------------------------
// Kernel 2: fp16 HMMA GEMM, 128 threads = 4 warps in 2x2 grid of 64x64 tiles.
// Minimal LDSM redundancy (A x2, B x2); 2 CTAs/SM.
// ---------------------------------------------------------------------------
__global__ void __launch_bounds__(128, 2)
gemm_kernel(float* __restrict__ out,
            const float* __restrict__ scale, const float* __restrict__ iscale) {
    extern __shared__ char smem[];
    uint32_t sb = s2u(smem);
    int tid = threadIdx.x;
    int wid = tid >> 5, lid = tid & 31;
    int wm = wid >> 1, wn = wid & 1;          // 2x2 warps, 64x64 each

    int tm = blockIdx.x & (MM / BM - 1);      // m fast -> ktile slices stay in L2
    int tn = blockIdx.x >> 6;                 // MM/BM = 64

    // per-thread cp.async bases (row = tid>>3 in 16-row group, ch = tid&7)
    int prow = tid >> 3, pch = tid & 7;
    const char* aptr = reinterpret_cast<const char*>(g_xq)
                     + (size_t)(tm * BM + prow) * ROW_BYTES + pch * 16;
    const char* bptr = reinterpret_cast<const char*>(g_wb)
                     + (size_t)(tn * BN + prow) * ROW_BYTES + pch * 16;
    uint32_t dbase_a = (uint32_t)prow * 128
                     + ((uint32_t)(pch ^ (prow & 7)) << 4);
    uint32_t dbase_b = dbase_a + A_TILE_BYTES;

    float acc[4][8][4];                        // [m16][n8][frag] = 128 regs
#pragma unroll
    for (int i = 0; i < 4; ++i)
#pragma unroll
        for (int j = 0; j < 8; ++j)
#pragma unroll
            for (int k = 0; k < 4; ++k) acc[i][j][k] = 0.0f;

    // per-lane LDSM base offsets and swizzle XOR terms
    int lrow = lid & 15;
    uint32_t lhish = (uint32_t)(lid >> 4) << 4;
    uint32_t aoff[4], axor[4], boff[4], bxor[4];
#pragma unroll
    for (int mt = 0; mt < 4; ++mt) {
        int row = wm * 64 + mt * 16 + lrow;
        aoff[mt] = (uint32_t)row * 128;
        axor[mt] = (uint32_t)(row & 7) << 4;
    }
#pragma unroll
    for (int p = 0; p < 4; ++p) {
        int row = wn * 64 + p * 16 + lrow;
        boff[p] = (uint32_t)row * 128;
        bxor[p] = (uint32_t)(row & 7) << 4;
    }

    // prologue: fill STAGES-1 stages (8 A-chunks + 8 B-chunks per thread)
#pragma unroll
    for (int s = 0; s < STAGES - 1; ++s) {
#pragma unroll
        for (int i = 0; i < 8; ++i)
            cpa16(sb + s * STAGE_BYTES + dbase_a + i * I_SSTRIDE,
                  aptr + i * I_GSTRIDE);
#pragma unroll
        for (int i = 0; i < 8; ++i)
            cpa16(sb + s * STAGE_BYTES + dbase_b + i * I_SSTRIDE,
                  bptr + i * I_GSTRIDE);
        asm volatile("cp.async.commit_group;" ::: "memory");
        aptr += BK * 2;
        bptr += BK * 2;
    }

    uint32_t cur = sb;
    uint32_t lda = sb + (STAGES - 1) * STAGE_BYTES + dbase_a;
    uint32_t ldb = sb + (STAGES - 1) * STAGE_BYTES + dbase_b;
    const uint32_t wrap = sb + STAGES * STAGE_BYTES;

    for (int kt = 0; kt < NKT; ++kt) {
        asm volatile("cp.async.wait_group %0;" :: "n"(STAGES - 2) : "memory");
        __syncthreads();

        uint32_t sa = cur, sbw = cur + A_TILE_BYTES;

        // j = 0 fragments first: restart the tensor pipe immediately
        uint32_t fa[4][4], fb[4][4];
#pragma unroll
        for (int mt = 0; mt < 4; ++mt)
            ldsm_x4(fa[mt][0], fa[mt][1], fa[mt][2], fa[mt][3],
                    sa + aoff[mt] + (lhish ^ axor[mt]));
#pragma unroll
        for (int p = 0; p < 4; ++p)
            ldsm_x4(fb[p][0], fb[p][1], fb[p][2], fb[p][3],
                    sbw + boff[p] + (lhish ^ bxor[p]));

        // issue next tile's loads (cheap addressing: base + imm)
        if (kt < NKT - (STAGES - 1)) {
#pragma unroll
            for (int i = 0; i < 8; ++i)
                cpa16(lda + i * I_SSTRIDE, aptr + i * I_GSTRIDE);
#pragma unroll
            for (int i = 0; i < 8; ++i)
                cpa16(ldb + i * I_SSTRIDE, bptr + i * I_GSTRIDE);
            aptr += BK * 2;
            bptr += BK * 2;
        }
        asm volatile("cp.async.commit_group;" ::: "memory");

#pragma unroll
        for (int j = 0; j < 4; ++j) {          // 4 k-steps of 16
            uint32_t ga[4][4], gb[4][4];
#pragma unroll
            for (int mt = 0; mt < 4; ++mt)
#pragma unroll
                for (int p = 0; p < 4; ++p) {
                    hmma(acc[mt][2 * p],     fa[mt][0], fa[mt][1], fa[mt][2],
                         fa[mt][3], fb[p][0], fb[p][2]);
                    hmma(acc[mt][2 * p + 1], fa[mt][0], fa[mt][1], fa[mt][2],
                         fa[mt][3], fb[p][1], fb[p][3]);
                }
            if (j < 3) {
                uint32_t chsh = ((uint32_t)(2 * (j + 1)) << 4) ^ lhish;
#pragma unroll
                for (int mt = 0; mt < 4; ++mt)
                    ldsm_x4(ga[mt][0], ga[mt][1], ga[mt][2], ga[mt][3],
                            sa + aoff[mt] + (chsh ^ axor[mt]));
#pragma unroll
                for (int p = 0; p < 4; ++p)
                    ldsm_x4(gb[p][0], gb[p][1], gb[p][2], gb[p][3],
                            sbw + boff[p] + (chsh ^ bxor[p]));
#pragma unroll
                for (int mt = 0; mt < 4; ++mt)
#pragma unroll
                    for (int q = 0; q < 4; ++q) fa[mt][q] = ga[mt][q];
#pragma unroll
                for (int p = 0; p < 4; ++p)
#pragma unroll
                    for (int q = 0; q < 4; ++q) fb[p][q] = gb[p][q];
            }
        }

        cur += STAGE_BYTES; if (cur == wrap) cur = sb;
        lda += STAGE_BYTES; if (lda >= wrap) lda -= STAGES * STAGE_BYTES;
        ldb += STAGE_BYTES; if (ldb >= wrap) ldb -= STAGES * STAGE_BYTES;
    }

    // epilogue: scale and store fp32
    float cs = scale[0] * iscale[0];
    int r0 = lid >> 2, c0 = (lid & 3) * 2;
#pragma unroll
    for (int mt = 0; mt < 4; ++mt) {
        size_t row0 = (size_t)tm * BM + wm * 64 + mt * 16 + r0;
#pragma unroll
        for (int nt = 0; nt < 8; ++nt) {
            size_t col = (size_t)tn * BN + wn * 64 + nt * 8 + c0;
            float2 v0, v1;
            v0.x = acc[mt][nt][0] * cs;
            v0.y = acc[mt][nt][1] * cs;
            v1.x = acc[mt][nt][2] * cs;
            v1.y = acc[mt][nt][3] * cs;
            *reinterpret_cast<float2*>(out + row0 * NN + col) = v0;
            *reinterpret_cast<float2*>(out + (row0 + 8) * NN + col) = v1;
        }
    }
}

// ---------------------------------------------------------------------------
extern "C" void kernel_launch(void* const* d_in, const int* in_sizes, int n_in,
                              void* d_out, int out_size) {
    const float* x      = (const float*)d_in[0];
    const int*   w      = (const int*)d_in[1];
    const float* scale  = (const float*)d_in[2];
    const float* iscale = (const float*)d_in[3];
    float* out = (float*)d_out;

    cudaFuncSetAttribute(gemm_kernel, cudaFuncAttributeMaxDynamicSharedMemorySize,
                         SMEM_TOTAL);

    prep_kernel<<<XBLK + WBLK, 256>>>(x, w, iscale);
    gemm_kernel<<<(MM / BM) * (NN / BN), 128, SMEM_TOTAL>>>(out, scale, iscale);
}